// round 6
// baseline (speedup 1.0000x reference)
#include <cuda_runtime.h>
#include <cstdint>

#define B_  8
#define C_  1024
#define T_  1024
#define H_  16
#define KC_ 64

__device__ float g_q[(size_t)B_*H_*T_*KC_];   // [b][h][t][ch_perm] tf32 (scaled)
__device__ float g_k[(size_t)B_*H_*T_*KC_];   // [b][h][t][ch_perm] tf32
__device__ float g_v[(size_t)B_*H_*T_*KC_];   // [b][h][s][ch] raw
__device__ float g_attn[(size_t)B_*T_*C_];    // [b][t][c_perm] tf32
__device__ float g_xT[(size_t)2*B_*T_*C_];    // [plane][t][c_perm] tf32
__device__ float g_wp[(size_t)4*C_*C_];       // [mat][o][c_perm] tf32

__device__ __forceinline__ float to_tf32(float x) {
    float r; asm("cvt.rna.tf32.f32 %0, %1;" : "=f"(r) : "f"(x)); return r;
}
__device__ __forceinline__ uint32_t fu(float x) { return __float_as_uint(x); }
__device__ __forceinline__ int p16f(int c) {
    return (c & ~15) | ((c & 3) << 2) | ((c & 15) >> 2);
}
__device__ __forceinline__ int swz4(int r, int ch) {
    return ((ch & ~7) | ((ch & 7) ^ (((r & 1) << 2) | ((r & 7) >> 1)))) << 2;
}
__device__ __forceinline__ void mma_tf32(float* c, const uint32_t* a, const uint32_t* b) {
    asm volatile(
        "mma.sync.aligned.m16n8k8.row.col.f32.tf32.tf32.f32 "
        "{%0,%1,%2,%3}, {%4,%5,%6,%7}, {%8,%9}, {%0,%1,%2,%3};"
        : "+f"(c[0]), "+f"(c[1]), "+f"(c[2]), "+f"(c[3])
        : "r"(a[0]), "r"(a[1]), "r"(a[2]), "r"(a[3]), "r"(b[0]), "r"(b[1]));
}
__device__ __forceinline__ void cpa16(uint32_t dst, const void* src) {
    asm volatile("cp.async.cg.shared.global [%0], [%1], 16;" :: "r"(dst), "l"(src));
}

// ---- prep: permute weights into g_wp ----
__global__ void prep_w(const float* __restrict__ w0, const float* __restrict__ w1,
                       const float* __restrict__ w2, const float* __restrict__ w3)
{
    int row = blockIdx.x, m = blockIdx.y, tid = threadIdx.x;
    const float* src = (m==0)?w0:(m==1)?w1:(m==2)?w2:w3;
    float4 v = *(const float4*)(src + (size_t)row*C_ + tid*4);
    float vv[4] = {v.x, v.y, v.z, v.w};
    float* dst = g_wp + ((size_t)m*C_ + row)*C_ + ((tid*4) & ~15);
    int u = tid & 3;
    #pragma unroll
    for (int j = 0; j < 4; j++) dst[4*j + u] = to_tf32(vv[j]);
}

// ---- prep: transpose x/c -> g_xT[plane][t][c_perm] ----
__global__ __launch_bounds__(256) void prep_x(const float* __restrict__ x,
                                              const float* __restrict__ cc)
{
    __shared__ float tile[32][33];
    int bb = blockIdx.z;
    const float* src = (bb < B_) ? x : cc;
    int b = bb & 7;
    int t0 = blockIdx.x*32, c0 = blockIdx.y*32;
    int tid = threadIdx.x;
    {
        int cl = tid >> 3, tq = (tid & 7) * 4;
        float4 v = *(const float4*)(src + ((size_t)b*C_ + c0+cl)*T_ + t0 + tq);
        tile[cl][tq+0] = v.x; tile[cl][tq+1] = v.y;
        tile[cl][tq+2] = v.z; tile[cl][tq+3] = v.w;
    }
    __syncthreads();
    {
        int tl = tid >> 3, cq = (tid & 7) * 4, u = (tid & 7) & 3;
        float* dst = g_xT + ((size_t)bb*T_ + t0+tl)*C_ + c0 + (cq & 16);
        #pragma unroll
        for (int j = 0; j < 4; j++) dst[4*j + u] = to_tf32(tile[cq+j][tl]);
    }
}

// ---- GEMM with 2-stage cp.async pipeline; 2 blocks/SM ----
#define GM_SMEM_BYTES (2*2*128*32*4)   // 2 stages x (A+B) x 16KB = 64KB

__global__ __launch_bounds__(256, 2) void gemm_mma(
    const float* __restrict__ bias, float* __restrict__ dout, float scale, int mode)
{
    extern __shared__ float smem[];
    float* As = smem;                 // [2][128*32]
    float* Bs = smem + 2*128*32;      // [2][128*32]

    const float* A = g_wp + (size_t)mode * C_ * C_;
    const float* Bm = (mode == 3) ? g_attn + (size_t)blockIdx.z*T_*C_
                    : g_xT + ((size_t)((mode?B_:0) + blockIdx.z))*T_*C_;
    const int b = blockIdx.z, o0 = blockIdx.y*128, t0 = blockIdx.x*128;
    const int tid = threadIdx.x, lane = tid & 31, w = tid >> 5;
    const int wm = (w >> 1) * 32, wn = (w & 1) * 64;
    const int gid = lane >> 2, tig = lane & 3;

    float acc[2][8][4];
    #pragma unroll
    for (int mt = 0; mt < 2; mt++)
        #pragma unroll
        for (int nt = 0; nt < 8; nt++)
            #pragma unroll
            for (int r = 0; r < 4; r++) acc[mt][nt][r] = 0.f;

    const int lr = tid & 127, lh = tid >> 7;
    const float* Ap = A  + (size_t)(o0 + lr)*C_ + lh*16;
    const float* Bp = Bm + (size_t)(t0 + lr)*C_ + lh*16;
    const uint32_t aBase = (uint32_t)__cvta_generic_to_shared(As);
    const uint32_t bBase = (uint32_t)__cvta_generic_to_shared(Bs);
    int offs[4];
    #pragma unroll
    for (int i = 0; i < 4; i++) offs[i] = lr*32 + swz4(lr, lh*4 + i);

    // prologue: stage 0
    #pragma unroll
    for (int i = 0; i < 4; i++) {
        cpa16(aBase + offs[i]*4, Ap + 4*i);
        cpa16(bBase + offs[i]*4, Bp + 4*i);
    }
    asm volatile("cp.async.commit_group;");

    int buf = 0;
    for (int k0 = 0; k0 < C_; k0 += 32) {
        const bool next = (k0 + 32 < C_);
        if (next) {
            int bo = (buf^1) * 4096;
            #pragma unroll
            for (int i = 0; i < 4; i++) {
                cpa16(aBase + (bo + offs[i])*4, Ap + k0 + 32 + 4*i);
                cpa16(bBase + (bo + offs[i])*4, Bp + k0 + 32 + 4*i);
            }
            asm volatile("cp.async.commit_group;");
            asm volatile("cp.async.wait_group 1;");
        } else {
            asm volatile("cp.async.wait_group 0;");
        }
        __syncthreads();

        const float* Asb = As + buf*4096;
        const float* Bsb = Bs + buf*4096;
        #pragma unroll
        for (int g = 0; g < 2; g++) {
            uint32_t aX[2][4], aY[2][4];
            #pragma unroll
            for (int mt = 0; mt < 2; mt++) {
                int r1 = wm + 16*mt + gid, r2 = r1 + 8;
                float4 qa = *(const float4*)&Asb[r1*32 + swz4(r1, g*4+tig)];
                float4 qb = *(const float4*)&Asb[r2*32 + swz4(r2, g*4+tig)];
                aX[mt][0]=fu(qa.x); aX[mt][1]=fu(qb.x); aX[mt][2]=fu(qa.y); aX[mt][3]=fu(qb.y);
                aY[mt][0]=fu(qa.z); aY[mt][1]=fu(qb.z); aY[mt][2]=fu(qa.w); aY[mt][3]=fu(qb.w);
            }
            #pragma unroll
            for (int nt = 0; nt < 8; nt++) {
                int rn = wn + 8*nt + gid;
                float4 kb = *(const float4*)&Bsb[rn*32 + swz4(rn, g*4+tig)];
                uint32_t bX[2] = {fu(kb.x), fu(kb.y)};
                uint32_t bY[2] = {fu(kb.z), fu(kb.w)};
                mma_tf32(acc[0][nt], aX[0], bX);
                mma_tf32(acc[0][nt], aY[0], bY);
                mma_tf32(acc[1][nt], aX[1], bX);
                mma_tf32(acc[1][nt], aY[1], bY);
            }
        }
        __syncthreads();
        buf ^= 1;
    }

    if (mode == 3) {
        #pragma unroll
        for (int mt = 0; mt < 2; mt++) {
            int oa = o0 + wm + 16*mt + gid, ob = oa + 8;
            float ba = bias[oa], bb2 = bias[ob];
            #pragma unroll
            for (int nt = 0; nt < 8; nt++) {
                int t = t0 + wn + 8*nt + 2*tig;
                float2 v01 = make_float2(acc[mt][nt][0] + ba,  acc[mt][nt][1] + ba);
                float2 v23 = make_float2(acc[mt][nt][2] + bb2, acc[mt][nt][3] + bb2);
                *(float2*)(dout + ((size_t)b*C_ + oa)*T_ + t) = v01;
                *(float2*)(dout + ((size_t)b*C_ + ob)*T_ + t) = v23;
            }
        }
    } else if (mode == 2) {
        #pragma unroll
        for (int mt = 0; mt < 2; mt++) {
            int oa = o0 + wm + 16*mt + gid, ob = oa + 8;
            float ba = bias[oa], bb2 = bias[ob];
            float* pa = g_v + ((size_t)b*H_ + (oa>>6))*T_*KC_;
            float* pb = g_v + ((size_t)b*H_ + (ob>>6))*T_*KC_;
            int ca = oa & 63, cb = ob & 63;
            #pragma unroll
            for (int nt = 0; nt < 8; nt++) {
                int t = t0 + wn + 8*nt + 2*tig;
                pa[(size_t)t    *KC_ + ca] = acc[mt][nt][0] + ba;
                pa[(size_t)(t+1)*KC_ + ca] = acc[mt][nt][1] + ba;
                pb[(size_t)t    *KC_ + cb] = acc[mt][nt][2] + bb2;
                pb[(size_t)(t+1)*KC_ + cb] = acc[mt][nt][3] + bb2;
            }
        }
    } else {
        float* outp = (mode == 0) ? g_q : g_k;
        #pragma unroll
        for (int mt = 0; mt < 2; mt++) {
            int oa = o0 + wm + 16*mt + gid, ob = oa + 8;
            float ba = bias[oa], bb2 = bias[ob];
            float* pa = outp + ((size_t)b*H_ + (oa>>6))*T_*KC_;
            float* pb = outp + ((size_t)b*H_ + (ob>>6))*T_*KC_;
            int ca = p16f(oa & 63), cb = p16f(ob & 63);
            #pragma unroll
            for (int nt = 0; nt < 8; nt++) {
                int t = t0 + wn + 8*nt + 2*tig;
                pa[(size_t)t    *KC_ + ca] = to_tf32((acc[mt][nt][0] + ba) * scale);
                pa[(size_t)(t+1)*KC_ + ca] = to_tf32((acc[mt][nt][1] + ba) * scale);
                pb[(size_t)t    *KC_ + cb] = to_tf32((acc[mt][nt][2] + bb2) * scale);
                pb[(size_t)(t+1)*KC_ + cb] = to_tf32((acc[mt][nt][3] + bb2) * scale);
            }
        }
    }
}

// ---- flash attention: unchanged from round 5 (passing) ----
#define FL_SMEM_FLOATS (128*64 + 64*64 + 64*68 + 128*64 + 576 + 128*12)
#define FL_SMEM_BYTES  (FL_SMEM_FLOATS * 4)

__global__ __launch_bounds__(256) void flash_mma(const float* __restrict__ emb)
{
    extern __shared__ float sm[];
    float* Qs = sm;               // [128][64] permuted+swizzled
    float* Ks = Qs + 128*64;      // [64][64]
    float* Vs = Ks + 64*64;       // [64][68]  raw rows s
    float* Ps = Vs + 64*68;       // [128][64] permuted+swizzled
    float* Eb = Ps + 128*64;      // [9][64] permuted
    float* Rb = Eb + 576;         // [128][12]

    const int b = blockIdx.z, h = blockIdx.y, q0 = blockIdx.x * 128;
    const int tid = threadIdx.x, lane = tid & 31, w = tid >> 5;
    const int gid = lane >> 2, tig = lane & 3;
    const int wr = 16 * w;
    const int R1 = wr + gid, R2 = R1 + 8;

    const size_t bh = ((size_t)b * H_ + h) * T_ * KC_;
    const float* Qg = g_q + bh;
    const float* Kg = g_k + bh;
    const float* Vg = g_v + bh;

    {
        int row = tid & 127, half = tid >> 7;
        #pragma unroll
        for (int i = 0; i < 8; i++) {
            int chk = half*8 + i;
            *(float4*)&Qs[row*64 + swz4(row, chk)] =
                *(const float4*)(Qg + (size_t)(q0 + row)*64 + chk*4);
        }
    }
    if (tid < 144) {
        float4 v = ((const float4*)emb)[tid];
        float vv[4] = {v.x, v.y, v.z, v.w};
        int j = tid >> 4, c = (tid & 15) * 4;
        #pragma unroll
        for (int u = 0; u < 4; u++) Eb[j*64 + p16f(c+u)] = vv[u];
    }
    __syncthreads();

    {
        int r = tid & 127;
        for (int j = tid >> 7; j < 9; j += 2) {
            float s = 0.f;
            #pragma unroll
            for (int c8 = 0; c8 < 16; c8++) {
                float4 qv = *(const float4*)&Qs[r*64 + swz4(r, c8)];
                const float* e = Eb + j*64 + c8*4;
                s += qv.x*e[0] + qv.y*e[1] + qv.z*e[2] + qv.w*e[3];
            }
            Rb[r*12 + j] = s;
        }
    }
    __syncthreads();

    float4 fq1[4], fq2[4];
    #pragma unroll
    for (int g = 0; g < 4; g++) {
        fq1[g] = *(const float4*)&Qs[R1*64 + swz4(R1, g*4+tig)];
        fq2[g] = *(const float4*)&Qs[R2*64 + swz4(R2, g*4+tig)];
    }

    float m1 = -1e30f, m2 = -1e30f, l1 = 0.f, l2 = 0.f;
    float o[8][4];
    #pragma unroll
    for (int nt = 0; nt < 8; nt++)
        #pragma unroll
        for (int r = 0; r < 4; r++) o[nt][r] = 0.f;

    for (int k0 = 0; k0 < T_; k0 += 64) {
        __syncthreads();
        {
            int row = tid & 63, qtr = tid >> 6;
            #pragma unroll
            for (int i = 0; i < 4; i++) {
                int chk = qtr*4 + i;
                *(float4*)&Ks[row*64 + swz4(row, chk)] =
                    *(const float4*)(Kg + (size_t)(k0 + row)*64 + chk*4);
            }
            int r = tid >> 2, c0 = (tid & 3) * 16;
            #pragma unroll
            for (int i = 0; i < 4; i++) {
                float4 vv = *(const float4*)(Vg + (size_t)(k0 + r)*64 + c0 + 4*i);
                vv.x = to_tf32(vv.x); vv.y = to_tf32(vv.y);
                vv.z = to_tf32(vv.z); vv.w = to_tf32(vv.w);
                *(float4*)&Vs[r*68 + c0 + 4*i] = vv;
            }
        }
        __syncthreads();

        float sc[8][4];
        #pragma unroll
        for (int nt = 0; nt < 8; nt++)
            #pragma unroll
            for (int r = 0; r < 4; r++) sc[nt][r] = 0.f;

        #pragma unroll
        for (int g = 0; g < 4; g++) {
            uint32_t aX[4] = {fu(fq1[g].x), fu(fq2[g].x), fu(fq1[g].y), fu(fq2[g].y)};
            uint32_t aY[4] = {fu(fq1[g].z), fu(fq2[g].z), fu(fq1[g].w), fu(fq2[g].w)};
            #pragma unroll
            for (int nt = 0; nt < 8; nt++) {
                int rn = 8*nt + gid;
                float4 kb = *(const float4*)&Ks[rn*64 + swz4(rn, g*4+tig)];
                uint32_t bX[2] = {fu(kb.x), fu(kb.y)};
                uint32_t bY[2] = {fu(kb.z), fu(kb.w)};
                mma_tf32(sc[nt], aX, bX);
                mma_tf32(sc[nt], aY, bY);
            }
        }

        const int t1 = q0 + R1, t2 = q0 + R2;
        #pragma unroll
        for (int nt = 0; nt < 8; nt++) {
            int s0 = k0 + 8*nt + 2*tig;
            int d0 = min(max(s0   - t1, -4), 4) + 4;
            int d1 = min(max(s0+1 - t1, -4), 4) + 4;
            int d2 = min(max(s0   - t2, -4), 4) + 4;
            int d3 = min(max(s0+1 - t2, -4), 4) + 4;
            sc[nt][0] += Rb[R1*12 + d0];
            sc[nt][1] += Rb[R1*12 + d1];
            sc[nt][2] += Rb[R2*12 + d2];
            sc[nt][3] += Rb[R2*12 + d3];
        }

        float mx1 = -1e30f, mx2 = -1e30f;
        #pragma unroll
        for (int nt = 0; nt < 8; nt++) {
            mx1 = fmaxf(mx1, fmaxf(sc[nt][0], sc[nt][1]));
            mx2 = fmaxf(mx2, fmaxf(sc[nt][2], sc[nt][3]));
        }
        mx1 = fmaxf(mx1, __shfl_xor_sync(0xffffffffu, mx1, 1));
        mx1 = fmaxf(mx1, __shfl_xor_sync(0xffffffffu, mx1, 2));
        mx2 = fmaxf(mx2, __shfl_xor_sync(0xffffffffu, mx2, 1));
        mx2 = fmaxf(mx2, __shfl_xor_sync(0xffffffffu, mx2, 2));
        float mn1 = fmaxf(m1, mx1), mn2 = fmaxf(m2, mx2);

        float rs1 = 0.f, rs2 = 0.f;
        #pragma unroll
        for (int nt = 0; nt < 8; nt++) {
            float p0 = __expf(sc[nt][0] - mn1);
            float p1 = __expf(sc[nt][1] - mn1);
            float p2 = __expf(sc[nt][2] - mn2);
            float p3 = __expf(sc[nt][3] - mn2);
            rs1 += p0 + p1; rs2 += p2 + p3;
            int f0 = 8*nt + 2*tig;
            int pA = p16f(f0), pB = p16f(f0 + 1);
            Ps[R1*64 + swz4(R1, pA>>2) + (pA&3)] = to_tf32(p0);
            Ps[R1*64 + swz4(R1, pB>>2) + (pB&3)] = to_tf32(p1);
            Ps[R2*64 + swz4(R2, pA>>2) + (pA&3)] = to_tf32(p2);
            Ps[R2*64 + swz4(R2, pB>>2) + (pB&3)] = to_tf32(p3);
        }
        rs1 += __shfl_xor_sync(0xffffffffu, rs1, 1);
        rs1 += __shfl_xor_sync(0xffffffffu, rs1, 2);
        rs2 += __shfl_xor_sync(0xffffffffu, rs2, 1);
        rs2 += __shfl_xor_sync(0xffffffffu, rs2, 2);

        float f1 = __expf(m1 - mn1), f2 = __expf(m2 - mn2);
        l1 = l1 * f1 + rs1; l2 = l2 * f2 + rs2;
        m1 = mn1; m2 = mn2;
        #pragma unroll
        for (int nt = 0; nt < 8; nt++) {
            o[nt][0] *= f1; o[nt][1] *= f1;
            o[nt][2] *= f2; o[nt][3] *= f2;
        }
        __syncwarp();

        #pragma unroll
        for (int g = 0; g < 4; g++) {
            float4 pa = *(const float4*)&Ps[R1*64 + swz4(R1, g*4+tig)];
            float4 pb = *(const float4*)&Ps[R2*64 + swz4(R2, g*4+tig)];
            uint32_t aX[4] = {fu(pa.x), fu(pb.x), fu(pa.y), fu(pb.y)};
            uint32_t aY[4] = {fu(pa.z), fu(pb.z), fu(pa.w), fu(pb.w)};
            #pragma unroll
            for (int nt = 0; nt < 8; nt++) {
                int cn = 8*nt + gid;
                uint32_t bX[2] = {fu(Vs[(16*g+tig  )*68 + cn]), fu(Vs[(16*g+4+tig )*68 + cn])};
                uint32_t bY[2] = {fu(Vs[(16*g+8+tig)*68 + cn]), fu(Vs[(16*g+12+tig)*68 + cn])};
                mma_tf32(o[nt], aX, bX);
                mma_tf32(o[nt], aY, bY);
            }
        }
    }

    float i1 = 1.f / l1, i2 = 1.f / l2;
    __syncthreads();
    float* Os = sm;
    #pragma unroll
    for (int nt = 0; nt < 8; nt++) {
        int f0 = 8*nt + 2*tig;
        int pA = p16f(f0), pB = p16f(f0 + 1);
        Os[R1*64 + swz4(R1, pA>>2) + (pA&3)] = to_tf32(o[nt][0] * i1);
        Os[R1*64 + swz4(R1, pB>>2) + (pB&3)] = to_tf32(o[nt][1] * i1);
        Os[R2*64 + swz4(R2, pA>>2) + (pA&3)] = to_tf32(o[nt][2] * i2);
        Os[R2*64 + swz4(R2, pB>>2) + (pB&3)] = to_tf32(o[nt][3] * i2);
    }
    __syncthreads();
    float* outb = g_attn + (size_t)b*T_*C_ + (size_t)q0*C_ + h*64;
    for (int idx = tid; idx < 2048; idx += 256) {
        int row = idx >> 4, c8 = idx & 15;
        float4 v = *(const float4*)&Os[row*64 + swz4(row, c8)];
        *(float4*)(outb + (size_t)row*C_ + c8*4) = v;
    }
}

// ---------------------------------------------------------------------------
extern "C" void kernel_launch(void* const* d_in, const int* in_sizes, int n_in,
                              void* d_out, int out_size)
{
    const float* x   = (const float*)d_in[0];
    const float* c   = (const float*)d_in[1];
    const float* wq  = (const float*)d_in[2];
    const float* bq  = (const float*)d_in[3];
    const float* wk  = (const float*)d_in[4];
    const float* bk  = (const float*)d_in[5];
    const float* wv  = (const float*)d_in[6];
    const float* bv  = (const float*)d_in[7];
    const float* wo  = (const float*)d_in[8];
    const float* bo  = (const float*)d_in[9];
    const float* erk = (const float*)d_in[10];

    prep_w<<<dim3(C_, 4), 256>>>(wq, wk, wv, wo);
    prep_x<<<dim3(T_/32, C_/32, 2*B_), 256>>>(x, c);

    cudaFuncSetAttribute(gemm_mma,
                         cudaFuncAttributeMaxDynamicSharedMemorySize, GM_SMEM_BYTES);
    dim3 ggrid(T_/128, C_/128, B_), blk(256);
    gemm_mma<<<ggrid, blk, GM_SMEM_BYTES>>>(bq, nullptr, 0.125f, 0);  // Q pre-scaled
    gemm_mma<<<ggrid, blk, GM_SMEM_BYTES>>>(bk, nullptr, 1.0f,   1);  // K unscaled
    gemm_mma<<<ggrid, blk, GM_SMEM_BYTES>>>(bv, nullptr, 1.0f,   2);

    cudaFuncSetAttribute(flash_mma,
                         cudaFuncAttributeMaxDynamicSharedMemorySize, FL_SMEM_BYTES);
    flash_mma<<<dim3(T_/128, H_, B_), blk, FL_SMEM_BYTES>>>(erk);

    gemm_mma<<<ggrid, blk, GM_SMEM_BYTES>>>(bo, (float*)d_out, 1.0f, 3);
}

// round 7
// speedup vs baseline: 1.6632x; 1.6632x over previous
#include <cuda_runtime.h>
#include <cstdint>

#define B_  8
#define C_  1024
#define T_  1024
#define H_  16
#define KC_ 64

__device__ float g_q[(size_t)B_*H_*T_*KC_];   // [b][h][t][ch_perm] tf32 (scaled)
__device__ float g_k[(size_t)B_*H_*T_*KC_];   // [b][h][t][ch_perm] tf32
__device__ float g_v[(size_t)B_*H_*T_*KC_];   // [b][h][ch][t_perm] tf32
__device__ float g_attn[(size_t)B_*C_*T_];    // [b][c][t]

__device__ __forceinline__ float to_tf32(float x) {
    float r; asm("cvt.rna.tf32.f32 %0, %1;" : "=f"(r) : "f"(x)); return r;
}
__device__ __forceinline__ uint32_t fu(float x) { return __float_as_uint(x); }
// permute low-4 bits: c -> ((c&3)<<2)|((c&15)>>2), keep high bits
__device__ __forceinline__ int p16f(int c) {
    return (c & ~15) | ((c & 3) << 2) | ((c & 15) >> 2);
}
// bank swizzle: float offset of 16B chunk `ch` within row r (rows of 64 floats)
__device__ __forceinline__ int swz4(int r, int ch) {
    return ((ch & ~7) | ((ch & 7) ^ (((r & 1) << 2) | ((r & 7) >> 1)))) << 2;
}
__device__ __forceinline__ void mma_tf32(float* c, const uint32_t* a, const uint32_t* b) {
    asm volatile(
        "mma.sync.aligned.m16n8k8.row.col.f32.tf32.tf32.f32 "
        "{%0,%1,%2,%3}, {%4,%5,%6,%7}, {%8,%9}, {%0,%1,%2,%3};"
        : "+f"(c[0]), "+f"(c[1]), "+f"(c[2]), "+f"(c[3])
        : "r"(a[0]), "r"(a[1]), "r"(a[2]), "r"(a[3]), "r"(b[0]), "r"(b[1]));
}
__device__ __forceinline__ void cpa16(uint32_t dst, const void* src) {
    asm volatile("cp.async.ca.shared.global [%0], [%1], 16;" :: "r"(dst), "l"(src));
}

// ---------------------------------------------------------------------------
// Projection GEMM (round-2 mainloop, measured fastest):
//   out[b,o,t] = sum_c W[o,c] * X[b,c,t] + bias[o]
// Epilogues write flash-friendly layouts.
// ---------------------------------------------------------------------------
__global__ __launch_bounds__(256) void gemm_mma(
    const float* __restrict__ W, const float* __restrict__ Xin,
    const float* __restrict__ bias, float* __restrict__ dout,
    float scale, int mode)
{
    const float* X = (mode == 3) ? (const float*)g_attn : Xin;
    const int b  = blockIdx.z;
    const int o0 = blockIdx.y * 128;
    const int t0 = blockIdx.x * 128;
    const int tid = threadIdx.x, lane = tid & 31, w = tid >> 5;
    const int wm = (w >> 1) * 32, wn = (w & 1) * 64;
    const int gid = lane >> 2, tig = lane & 3;

    __shared__ float As[32][132];   // [k][o]
    __shared__ float Bs[32][132];   // [k][t]

    float acc[2][8][4];
    #pragma unroll
    for (int mt = 0; mt < 2; mt++)
        #pragma unroll
        for (int nt = 0; nt < 8; nt++)
            #pragma unroll
            for (int r = 0; r < 4; r++) acc[mt][nt][r] = 0.f;

    const float* Xb = X + (size_t)b * C_ * T_;
    const int am = tid >> 1, ak = (tid & 1) * 16;
    const int bk = tid >> 3, bn = (tid & 7) * 16;
    const float* Wp = W  + (size_t)(o0 + am) * C_ + ak;
    const float* Xp = Xb + (size_t)bk * T_ + t0 + bn;

    for (int k0 = 0; k0 < C_; k0 += 32) {
        #pragma unroll
        for (int i = 0; i < 4; i++) {
            float4 wv = *(const float4*)(Wp + k0 + 4*i);
            As[ak+4*i+0][am] = to_tf32(wv.x);
            As[ak+4*i+1][am] = to_tf32(wv.y);
            As[ak+4*i+2][am] = to_tf32(wv.z);
            As[ak+4*i+3][am] = to_tf32(wv.w);
            float4 xv = *(const float4*)(Xp + (size_t)k0 * T_ + 4*i);
            xv.x = to_tf32(xv.x); xv.y = to_tf32(xv.y);
            xv.z = to_tf32(xv.z); xv.w = to_tf32(xv.w);
            *(float4*)&Bs[bk][bn + 4*i] = xv;
        }
        __syncthreads();
        #pragma unroll
        for (int kk = 0; kk < 32; kk += 8) {
            uint32_t a[2][4], bf[8][2];
            #pragma unroll
            for (int mt = 0; mt < 2; mt++) {
                int m = wm + 16*mt + gid;
                a[mt][0] = fu(As[kk+tig  ][m  ]);
                a[mt][1] = fu(As[kk+tig  ][m+8]);
                a[mt][2] = fu(As[kk+4+tig][m  ]);
                a[mt][3] = fu(As[kk+4+tig][m+8]);
            }
            #pragma unroll
            for (int nt = 0; nt < 8; nt++) {
                int n = wn + 8*nt + gid;
                bf[nt][0] = fu(Bs[kk+tig  ][n]);
                bf[nt][1] = fu(Bs[kk+4+tig][n]);
            }
            #pragma unroll
            for (int mt = 0; mt < 2; mt++)
                #pragma unroll
                for (int nt = 0; nt < 8; nt++)
                    mma_tf32(acc[mt][nt], a[mt], bf[nt]);
        }
        __syncthreads();
    }

    if (mode == 3) {
        #pragma unroll
        for (int mt = 0; mt < 2; mt++) {
            int oa = o0 + wm + 16*mt + gid, ob = oa + 8;
            float ba = bias[oa], bb2 = bias[ob];
            #pragma unroll
            for (int nt = 0; nt < 8; nt++) {
                int t = t0 + wn + 8*nt + 2*tig;
                float2 v01 = make_float2(acc[mt][nt][0] + ba,  acc[mt][nt][1] + ba);
                float2 v23 = make_float2(acc[mt][nt][2] + bb2, acc[mt][nt][3] + bb2);
                *(float2*)(dout + ((size_t)b*C_ + oa)*T_ + t) = v01;
                *(float2*)(dout + ((size_t)b*C_ + ob)*T_ + t) = v23;
            }
        }
    } else if (mode == 2) {
        // g_v[b][h][ch][t_perm], tf32
        #pragma unroll
        for (int mt = 0; mt < 2; mt++) {
            int oa = o0 + wm + 16*mt + gid, ob = oa + 8;
            float ba = bias[oa], bb2 = bias[ob];
            float* pa = g_v + ((size_t)(b*H_ + (oa>>6))*KC_ + (oa & 63)) * T_;
            float* pb = g_v + ((size_t)(b*H_ + (ob>>6))*KC_ + (ob & 63)) * T_;
            #pragma unroll
            for (int nt = 0; nt < 8; nt++) {
                int t = t0 + wn + 8*nt + 2*tig;
                pa[p16f(t)  ] = to_tf32(acc[mt][nt][0] + ba);
                pa[p16f(t+1)] = to_tf32(acc[mt][nt][1] + ba);
                pb[p16f(t)  ] = to_tf32(acc[mt][nt][2] + bb2);
                pb[p16f(t+1)] = to_tf32(acc[mt][nt][3] + bb2);
            }
        }
    } else {
        // g_q / g_k: [b][h][t][ch_perm], tf32 (q pre-scaled)
        float* outp = (mode == 0) ? g_q : g_k;
        #pragma unroll
        for (int mt = 0; mt < 2; mt++) {
            int oa = o0 + wm + 16*mt + gid, ob = oa + 8;
            float ba = bias[oa], bb2 = bias[ob];
            float* pa = outp + ((size_t)b*H_ + (oa>>6))*T_*KC_;
            float* pb = outp + ((size_t)b*H_ + (ob>>6))*T_*KC_;
            int ca = p16f(oa & 63), cb = p16f(ob & 63);
            #pragma unroll
            for (int nt = 0; nt < 8; nt++) {
                int t = t0 + wn + 8*nt + 2*tig;
                pa[(size_t)t    *KC_ + ca] = to_tf32((acc[mt][nt][0] + ba) * scale);
                pa[(size_t)(t+1)*KC_ + ca] = to_tf32((acc[mt][nt][1] + ba) * scale);
                pb[(size_t)t    *KC_ + cb] = to_tf32((acc[mt][nt][2] + bb2) * scale);
                pb[(size_t)(t+1)*KC_ + cb] = to_tf32((acc[mt][nt][3] + bb2) * scale);
            }
        }
    }
}

// ---------------------------------------------------------------------------
// Flash attention: Q tile 128, KV tile 64, 8 warps.
// cp.async double-buffered K/V, one barrier per tile, P via shfl (no smem P).
// ---------------------------------------------------------------------------
#define FL_SMEM_FLOATS (128*64 + 2*64*64 + 2*64*64 + 576 + 128*12)
#define FL_SMEM_BYTES  (FL_SMEM_FLOATS * 4)

__global__ __launch_bounds__(256, 2) void flash_mma(const float* __restrict__ emb)
{
    extern __shared__ float sm[];
    float* Qs = sm;               // [128][64] swizzled (perm channels)
    float* Kb = Qs + 128*64;      // [2][64][64] swizzled
    float* Vb = Kb + 2*64*64;     // [2][64][64] swizzled (rows=ch, cols=t_perm)
    float* Eb = Vb + 2*64*64;     // [9][64] permuted
    float* Rb = Eb + 576;         // [128][12]

    const int b = blockIdx.z, h = blockIdx.y, q0 = blockIdx.x * 128;
    const int tid = threadIdx.x, lane = tid & 31, w = tid >> 5;
    const int gid = lane >> 2, tig = lane & 3;
    const int wr = 16 * w;
    const int R1 = wr + gid, R2 = R1 + 8;

    const size_t bh = ((size_t)b * H_ + h) * T_ * KC_;
    const float* Qg = g_q + bh;
    const float* Kg = g_k + bh;
    const float* Vg = g_v + bh;   // [ch][t_perm]

    const uint32_t kBase = (uint32_t)__cvta_generic_to_shared(Kb);
    const uint32_t vBase = (uint32_t)__cvta_generic_to_shared(Vb);
    const int cprow = tid >> 4;        // 0..15
    const int cpchk = tid & 15;        // 0..15
    int cpoff[4];
    #pragma unroll
    for (int i = 0; i < 4; i++) {
        int row = cprow + i*16;
        cpoff[i] = row*64 + swz4(row, cpchk);
    }

    // prologue: issue KV tile 0 into buf 0
    #pragma unroll
    for (int i = 0; i < 4; i++) {
        int row = cprow + i*16;
        cpa16(kBase + cpoff[i]*4, Kg + (size_t)row*64 + cpchk*4);
        cpa16(vBase + cpoff[i]*4, Vg + (size_t)row*T_ + cpchk*4);
    }
    asm volatile("cp.async.commit_group;");

    // Q tile copy (tf32+permuted in gmem) into swizzled Qs
    {
        int row = tid & 127, half = tid >> 7;
        #pragma unroll
        for (int i = 0; i < 8; i++) {
            int chk = half*8 + i;
            *(float4*)&Qs[row*64 + swz4(row, chk)] =
                *(const float4*)(Qg + (size_t)(q0 + row)*64 + chk*4);
        }
    }
    if (tid < 144) {
        float4 v = ((const float4*)emb)[tid];
        float vv[4] = {v.x, v.y, v.z, v.w};
        int j = tid >> 4, c = (tid & 15) * 4;
        #pragma unroll
        for (int u = 0; u < 4; u++) Eb[j*64 + p16f(c+u)] = vv[u];
    }
    __syncthreads();

    // Rb[r][j] = q_r . emb_j (both permuted consistently)
    {
        int r = tid & 127;
        for (int j = tid >> 7; j < 9; j += 2) {
            float s = 0.f;
            #pragma unroll
            for (int c8 = 0; c8 < 16; c8++) {
                float4 qv = *(const float4*)&Qs[r*64 + swz4(r, c8)];
                const float* e = Eb + j*64 + c8*4;
                s += qv.x*e[0] + qv.y*e[1] + qv.z*e[2] + qv.w*e[3];
            }
            Rb[r*12 + j] = s;
        }
    }

    float m1 = -1e30f, m2 = -1e30f, l1 = 0.f, l2 = 0.f;
    float o[8][4];
    #pragma unroll
    for (int nt = 0; nt < 8; nt++)
        #pragma unroll
        for (int r = 0; r < 4; r++) o[nt][r] = 0.f;

    int buf = 0;
    for (int it = 0; it < 16; it++) {
        const int k0 = it * 64;
        asm volatile("cp.async.wait_group 0;");
        __syncthreads();   // KV tile `it` visible to all; prior reads of buf^1 done

        if (it < 15) {
            int bo2 = (buf^1) * 4096;
            #pragma unroll
            for (int i = 0; i < 4; i++) {
                int row = cprow + i*16;
                cpa16(kBase + (bo2 + cpoff[i])*4, Kg + (size_t)(k0+64+row)*64 + cpchk*4);
                cpa16(vBase + (bo2 + cpoff[i])*4, Vg + (size_t)row*T_ + (k0+64) + cpchk*4);
            }
            asm volatile("cp.async.commit_group;");
        }

        const float* Kt = Kb + buf*4096;
        const float* Vt = Vb + buf*4096;

        // S = Q K^T
        float sc[8][4];
        #pragma unroll
        for (int nt = 0; nt < 8; nt++)
            #pragma unroll
            for (int r = 0; r < 4; r++) sc[nt][r] = 0.f;

        #pragma unroll
        for (int g = 0; g < 4; g++) {
            float4 qa = *(const float4*)&Qs[R1*64 + swz4(R1, g*4+tig)];
            float4 qb = *(const float4*)&Qs[R2*64 + swz4(R2, g*4+tig)];
            uint32_t aX[4] = {fu(qa.x), fu(qb.x), fu(qa.y), fu(qb.y)};
            uint32_t aY[4] = {fu(qa.z), fu(qb.z), fu(qa.w), fu(qb.w)};
            #pragma unroll
            for (int nt = 0; nt < 8; nt++) {
                int rn = 8*nt + gid;
                float4 kb = *(const float4*)&Kt[rn*64 + swz4(rn, g*4+tig)];
                uint32_t bX[2] = {fu(kb.x), fu(kb.y)};
                uint32_t bY[2] = {fu(kb.z), fu(kb.w)};
                mma_tf32(sc[nt], aX, bX);
                mma_tf32(sc[nt], aY, bY);
            }
        }

        // relative-position bias
        const int t1 = q0 + R1, t2 = q0 + R2;
        #pragma unroll
        for (int nt = 0; nt < 8; nt++) {
            int s0 = k0 + 8*nt + 2*tig;
            int d0 = min(max(s0   - t1, -4), 4) + 4;
            int d1 = min(max(s0+1 - t1, -4), 4) + 4;
            int d2 = min(max(s0   - t2, -4), 4) + 4;
            int d3 = min(max(s0+1 - t2, -4), 4) + 4;
            sc[nt][0] += Rb[R1*12 + d0];
            sc[nt][1] += Rb[R1*12 + d1];
            sc[nt][2] += Rb[R2*12 + d2];
            sc[nt][3] += Rb[R2*12 + d3];
        }

        // online softmax (rows R1, R2; reduce over 4 quad lanes)
        float mx1 = -1e30f, mx2 = -1e30f;
        #pragma unroll
        for (int nt = 0; nt < 8; nt++) {
            mx1 = fmaxf(mx1, fmaxf(sc[nt][0], sc[nt][1]));
            mx2 = fmaxf(mx2, fmaxf(sc[nt][2], sc[nt][3]));
        }
        mx1 = fmaxf(mx1, __shfl_xor_sync(0xffffffffu, mx1, 1));
        mx1 = fmaxf(mx1, __shfl_xor_sync(0xffffffffu, mx1, 2));
        mx2 = fmaxf(mx2, __shfl_xor_sync(0xffffffffu, mx2, 1));
        mx2 = fmaxf(mx2, __shfl_xor_sync(0xffffffffu, mx2, 2));
        float mn1 = fmaxf(m1, mx1), mn2 = fmaxf(m2, mx2);

        float rs1 = 0.f, rs2 = 0.f;
        #pragma unroll
        for (int nt = 0; nt < 8; nt++) {
            float p0 = __expf(sc[nt][0] - mn1);
            float p1 = __expf(sc[nt][1] - mn1);
            float p2 = __expf(sc[nt][2] - mn2);
            float p3 = __expf(sc[nt][3] - mn2);
            rs1 += p0 + p1; rs2 += p2 + p3;
            sc[nt][0] = to_tf32(p0); sc[nt][1] = to_tf32(p1);
            sc[nt][2] = to_tf32(p2); sc[nt][3] = to_tf32(p3);
        }
        rs1 += __shfl_xor_sync(0xffffffffu, rs1, 1);
        rs1 += __shfl_xor_sync(0xffffffffu, rs1, 2);
        rs2 += __shfl_xor_sync(0xffffffffu, rs2, 1);
        rs2 += __shfl_xor_sync(0xffffffffu, rs2, 2);

        float f1 = __expf(m1 - mn1), f2 = __expf(m2 - mn2);
        l1 = l1 * f1 + rs1; l2 = l2 * f2 + rs2;
        m1 = mn1; m2 = mn2;
        #pragma unroll
        for (int nt = 0; nt < 8; nt++) {
            o[nt][0] *= f1; o[nt][1] *= f1;
            o[nt][2] *= f2; o[nt][3] *= f2;
        }

        // O += P V ; P a-frags built from sc via quad shfl
        const int s1 = (lane & ~3) | (tig >> 1);
        const int s2 = s1 + 2;
        const bool od = (tig & 1);
        #pragma unroll
        for (int G = 0; G < 4; G++) {
            uint32_t aX[4], aY[4];
            {
                const float* p4 = sc[2*G];
                float q0v = __shfl_sync(0xffffffffu, p4[0], s1);
                float q1v = __shfl_sync(0xffffffffu, p4[1], s1);
                float q2v = __shfl_sync(0xffffffffu, p4[2], s1);
                float q3v = __shfl_sync(0xffffffffu, p4[3], s1);
                float r0v = __shfl_sync(0xffffffffu, p4[0], s2);
                float r1v = __shfl_sync(0xffffffffu, p4[1], s2);
                float r2v = __shfl_sync(0xffffffffu, p4[2], s2);
                float r3v = __shfl_sync(0xffffffffu, p4[3], s2);
                aX[0] = fu(od ? q1v : q0v); aX[1] = fu(od ? q3v : q2v);
                aX[2] = fu(od ? r1v : r0v); aX[3] = fu(od ? r3v : r2v);
            }
            {
                const float* p4 = sc[2*G+1];
                float q0v = __shfl_sync(0xffffffffu, p4[0], s1);
                float q1v = __shfl_sync(0xffffffffu, p4[1], s1);
                float q2v = __shfl_sync(0xffffffffu, p4[2], s1);
                float q3v = __shfl_sync(0xffffffffu, p4[3], s1);
                float r0v = __shfl_sync(0xffffffffu, p4[0], s2);
                float r1v = __shfl_sync(0xffffffffu, p4[1], s2);
                float r2v = __shfl_sync(0xffffffffu, p4[2], s2);
                float r3v = __shfl_sync(0xffffffffu, p4[3], s2);
                aY[0] = fu(od ? q1v : q0v); aY[1] = fu(od ? q3v : q2v);
                aY[2] = fu(od ? r1v : r0v); aY[3] = fu(od ? r3v : r2v);
            }
            #pragma unroll
            for (int nt = 0; nt < 8; nt++) {
                int cn = 8*nt + gid;
                float4 vb = *(const float4*)&Vt[cn*64 + swz4(cn, G*4+tig)];
                uint32_t bX[2] = {fu(vb.x), fu(vb.y)};
                uint32_t bY[2] = {fu(vb.z), fu(vb.w)};
                mma_tf32(o[nt], aX, bX);
                mma_tf32(o[nt], aY, bY);
            }
        }
        buf ^= 1;
    }

    float i1 = 1.f / l1, i2 = 1.f / l2;
    __syncthreads();                  // last tile's reads done; reuse Kb/Vb as Os
    float* Os = Kb;                   // [64][132] (8448 floats fit in Kb+Vb)
    #pragma unroll
    for (int nt = 0; nt < 8; nt++) {
        int ch = 8*nt + 2*tig;
        Os[(ch  )*132 + R1] = o[nt][0] * i1;
        Os[(ch+1)*132 + R1] = o[nt][1] * i1;
        Os[(ch  )*132 + R2] = o[nt][2] * i2;
        Os[(ch+1)*132 + R2] = o[nt][3] * i2;
    }
    __syncthreads();
    float* outb = g_attn + ((size_t)b * C_ + h * 64) * T_ + q0;
    for (int i = tid; i < 2048; i += 256) {
        int row = i >> 5, col = (i & 31) * 4;
        *(float4*)(outb + (size_t)row * T_ + col) = *(float4*)&Os[row*132 + col];
    }
}

// ---------------------------------------------------------------------------
extern "C" void kernel_launch(void* const* d_in, const int* in_sizes, int n_in,
                              void* d_out, int out_size)
{
    const float* x   = (const float*)d_in[0];
    const float* c   = (const float*)d_in[1];
    const float* wq  = (const float*)d_in[2];
    const float* bq  = (const float*)d_in[3];
    const float* wk  = (const float*)d_in[4];
    const float* bk  = (const float*)d_in[5];
    const float* wv  = (const float*)d_in[6];
    const float* bv  = (const float*)d_in[7];
    const float* wo  = (const float*)d_in[8];
    const float* bo  = (const float*)d_in[9];
    const float* erk = (const float*)d_in[10];

    dim3 ggrid(T_/128, C_/128, B_), blk(256);
    gemm_mma<<<ggrid, blk>>>(wq, x, bq, nullptr, 0.125f, 0);  // Q pre-scaled 1/sqrt(64)
    gemm_mma<<<ggrid, blk>>>(wk, c, bk, nullptr, 1.0f,   1);  // K UNSCALED
    gemm_mma<<<ggrid, blk>>>(wv, c, bv, nullptr, 1.0f,   2);

    cudaFuncSetAttribute(flash_mma,
                         cudaFuncAttributeMaxDynamicSharedMemorySize, FL_SMEM_BYTES);
    flash_mma<<<dim3(T_/128, H_, B_), blk, FL_SMEM_BYTES>>>(erk);

    gemm_mma<<<ggrid, blk>>>(wo, nullptr, bo, (float*)d_out, 1.0f, 3);
}